// round 10
// baseline (speedup 1.0000x reference)
#include <cuda_runtime.h>
#include <math.h>

#define H    1024
#define SRC  512
#define TGT  128
#define VOUT 32000
#define G3   3072

// ---------------- scratch (static device memory; no allocations) ----------------
__device__ float g_X   [SRC * H];      // gathered encoder inputs
__device__ float g_GIf [SRC * G3];     // precomputed input gates, forward
__device__ float g_GIb [SRC * G3];     // backward
__device__ float g_outsf[SRC * H];
__device__ float g_outsb[SRC * H];
__device__ float g_enc  [SRC * H];     // enc_out
__device__ float g_encT [H * SRC];     // enc_out transposed
__device__ float g_XT  [TGT * 2 * H];  // decoder inputs [ctx | emb]
__device__ float g_GId [TGT * G3];     // decoder input gates
__device__ float g_H2  [TGT * H];      // decoder hidden sequence
__device__ float g_ATT [TGT * SRC];
__device__ float g_CTX [TGT * H];
__device__ float g_CAT [TGT * 2 * H];
__device__ float g_henc[2][2][H];      // [dir][parity][H]
__device__ float g_hdec[2][H];         // [parity][H]
__device__ unsigned g_bar_e;
__device__ unsigned g_bar_d;

__device__ __forceinline__ float sigmoidf_(float x) { return 1.0f / (1.0f + expf(-x)); }

// ---------------- init: zero h state + barrier counters ----------------
__global__ void init_state() {
    int i = blockIdx.x * blockDim.x + threadIdx.x;
    if (i < 4 * H) ((float*)g_henc)[i] = 0.0f;
    if (i == 0) { g_bar_e = 0u; g_bar_d = 0u; }
}

// ---------------- gathers / concats ----------------
__global__ void gather_x(const int* __restrict__ wi, const float* __restrict__ emb) {
    int i = blockIdx.x * blockDim.x + threadIdx.x;
    if (i >= SRC * H) return;
    int t = i >> 10, c = i & (H - 1);
    g_X[i] = emb[(size_t)wi[t] * H + c];
}

__global__ void build_xt(const int* __restrict__ ctxi, const int* __restrict__ tgts,
                         const float* __restrict__ rarnn_emb, const float* __restrict__ dec_emb) {
    int i = blockIdx.x * blockDim.x + threadIdx.x;
    if (i >= TGT * 2 * H) return;
    int t = i >> 11, c = i & (2 * H - 1);
    float v;
    if (c < H) {
        v = rarnn_emb[(size_t)ctxi[0] * H + c];
    } else {
        int tok = (t == 0) ? 0 : tgts[t - 1];
        v = dec_emb[(size_t)tok * H + (c - H)];
    }
    g_XT[i] = v;
}

__global__ void build_cat() {
    int i = blockIdx.x * blockDim.x + threadIdx.x;
    if (i >= TGT * 2 * H) return;
    int t = i >> 11, c = i & (2 * H - 1);
    g_CAT[i] = (c < H) ? g_H2[t * H + c] : g_CTX[t * H + (c - H)];
}

// enc_out = outs_f + outs_b (+transpose); dec_h0 = h_f_final + h_b_final
__global__ void combine_enc() {
    int i = blockIdx.x * blockDim.x + threadIdx.x;
    if (i < SRC * H) {
        int t = i >> 10, c = i & (H - 1);
        float e = g_outsf[i] + g_outsb[i];
        g_enc[i] = e;
        g_encT[c * SRC + t] = e;
    }
    if (i < H) {
        g_hdec[0][i] = g_henc[0][0][i] + g_henc[1][0][i];  // final parity is 0 (512 steps)
    }
}

__global__ void copy_attn(float* __restrict__ out) {
    int i = blockIdx.x * blockDim.x + threadIdx.x;
    if (i >= (TGT - 1) * SRC) return;
    out[(size_t)TGT * VOUT + i] = g_ATT[i];  // first 127 rows, contiguous
}

// ---------------- SGEMM (NT): C[M,N] = A[M,K] * B[N,K]^T (+bias) (opt sigmoid) ----
// All M,N multiples of 128; K multiple of 16. 256 threads, 8x8 micro-tile.
template <int SIG>
__global__ void __launch_bounds__(256) sgemm_nt(const float* __restrict__ A,
                                                const float* __restrict__ B,
                                                const float* __restrict__ bias,
                                                float* __restrict__ C,
                                                int M, int N, int K) {
    __shared__ float As[16][132];
    __shared__ float Bs[16][132];
    const int bm = blockIdx.y * 128, bn = blockIdx.x * 128;
    const int tid = threadIdx.x;
    const int tx = tid & 15, ty = tid >> 4;

    float acc[8][8];
#pragma unroll
    for (int i = 0; i < 8; i++)
#pragma unroll
        for (int j = 0; j < 8; j++) acc[i][j] = 0.0f;

    for (int k0 = 0; k0 < K; k0 += 16) {
#pragma unroll
        for (int i = 0; i < 2; i++) {
            int idx = tid + i * 256;            // 0..511
            int row = idx >> 2;                 // 0..127
            int c4  = (idx & 3) * 4;            // 0,4,8,12
            float4 a = *(const float4*)&A[(size_t)(bm + row) * K + k0 + c4];
            As[c4 + 0][row] = a.x; As[c4 + 1][row] = a.y;
            As[c4 + 2][row] = a.z; As[c4 + 3][row] = a.w;
            float4 b = *(const float4*)&B[(size_t)(bn + row) * K + k0 + c4];
            Bs[c4 + 0][row] = b.x; Bs[c4 + 1][row] = b.y;
            Bs[c4 + 2][row] = b.z; Bs[c4 + 3][row] = b.w;
        }
        __syncthreads();
#pragma unroll
        for (int k = 0; k < 16; k++) {
            float4 a0 = *(const float4*)&As[k][ty * 4];
            float4 a1 = *(const float4*)&As[k][ty * 4 + 64];
            float4 b0 = *(const float4*)&Bs[k][tx * 4];
            float4 b1 = *(const float4*)&Bs[k][tx * 4 + 64];
            float av[8] = {a0.x, a0.y, a0.z, a0.w, a1.x, a1.y, a1.z, a1.w};
            float bv[8] = {b0.x, b0.y, b0.z, b0.w, b1.x, b1.y, b1.z, b1.w};
#pragma unroll
            for (int i = 0; i < 8; i++)
#pragma unroll
                for (int j = 0; j < 8; j++) acc[i][j] += av[i] * bv[j];
        }
        __syncthreads();
    }

#pragma unroll
    for (int i = 0; i < 8; i++) {
        int m = bm + ty * 4 + (i & 3) + ((i >> 2) << 6);
#pragma unroll
        for (int jj = 0; jj < 2; jj++) {
            int n0 = bn + tx * 4 + (jj << 6);
            float4 v;
            float b0 = bias ? bias[n0 + 0] : 0.0f;
            float b1 = bias ? bias[n0 + 1] : 0.0f;
            float b2 = bias ? bias[n0 + 2] : 0.0f;
            float b3 = bias ? bias[n0 + 3] : 0.0f;
            v.x = acc[i][jj * 4 + 0] + b0;
            v.y = acc[i][jj * 4 + 1] + b1;
            v.z = acc[i][jj * 4 + 2] + b2;
            v.w = acc[i][jj * 4 + 3] + b3;
            if (SIG) {
                v.x = sigmoidf_(v.x); v.y = sigmoidf_(v.y);
                v.z = sigmoidf_(v.z); v.w = sigmoidf_(v.w);
            }
            *(float4*)&C[(size_t)m * N + n0] = v;
        }
    }
}

// ---------------- grid barrier helper ----------------
// Release: ALL threads fence before syncthreads so every producer's writes are
// globally visible before thread 0 publishes arrival. Acquire: fence after spin.
__device__ __forceinline__ void grid_barrier(unsigned* ctr, unsigned target) {
    __threadfence();
    __syncthreads();
    if (threadIdx.x == 0) {
        atomicAdd(ctr, 1u);
        while (*(volatile unsigned*)ctr < target) { }
        __threadfence();
    }
    __syncthreads();
}

// ---------------- persistent encoder scan (both directions) ----------------
// 128 blocks x 256 threads; blocks 0..63 forward, 64..127 backward.
// Each block owns 16 hidden units; w_hh rows cached in smem (16*3*1024 f32 = 192KB).
__global__ void __launch_bounds__(256, 1) enc_scan(const float* __restrict__ whh_f,
                                                   const float* __restrict__ whh_b,
                                                   const float* __restrict__ bhh_f,
                                                   const float* __restrict__ bhh_b) {
    extern __shared__ float smem[];
    const int b   = blockIdx.x;
    const int dir = b >> 6;
    const int u0  = (b & 63) * 16;
    const float* whh = dir ? whh_b : whh_f;
    const float* bhh = dir ? bhh_b : bhh_f;
    float* wsm = smem;                       // [s][g][1024]
    float* bsm = smem + 16 * 3 * 1024;       // [s][g]

    for (int i = threadIdx.x; i < 16 * 3 * 1024; i += 256) {
        int s = i / G3, rem = i % G3, g = rem >> 10, c = rem & (H - 1);
        wsm[i] = whh[((size_t)(g * H + u0 + s)) * H + c];
    }
    if (threadIdx.x < 48) {
        int s = threadIdx.x / 3, g = threadIdx.x % 3;
        bsm[s * 3 + g] = bhh[g * H + u0 + s];
    }
    __syncthreads();

    const int lane = threadIdx.x & 31, w = threadIdx.x >> 5;
    const float* gi_base = dir ? g_GIb : g_GIf;
    float* outs = dir ? g_outsb : g_outsf;

    for (int t = 0; t < SRC; t++) {
        const int p = t & 1;
        const float4* hc = (const float4*)g_henc[dir][p];
        float4 hv[8];
#pragma unroll
        for (int j = 0; j < 8; j++) hv[j] = hc[lane + j * 32];

        float res[2][3];
#pragma unroll
        for (int su = 0; su < 2; su++) {
            int s = w * 2 + su;
            const float4* wr = (const float4*)(wsm + s * G3);
            const float4* wz = wr + 256;
            const float4* wn = wz + 256;
            float ar = 0.f, az = 0.f, an = 0.f;
#pragma unroll
            for (int j = 0; j < 8; j++) {
                float4 h4 = hv[j];
                float4 r4 = wr[lane + j * 32];
                ar += h4.x * r4.x + h4.y * r4.y + h4.z * r4.z + h4.w * r4.w;
                float4 z4 = wz[lane + j * 32];
                az += h4.x * z4.x + h4.y * z4.y + h4.z * z4.z + h4.w * z4.w;
                float4 n4 = wn[lane + j * 32];
                an += h4.x * n4.x + h4.y * n4.y + h4.z * n4.z + h4.w * n4.w;
            }
            res[su][0] = ar; res[su][1] = az; res[su][2] = an;
        }
#pragma unroll
        for (int o = 16; o > 0; o >>= 1) {
#pragma unroll
            for (int su = 0; su < 2; su++)
#pragma unroll
                for (int g = 0; g < 3; g++)
                    res[su][g] += __shfl_xor_sync(0xffffffffu, res[su][g], o);
        }
        if (lane < 2) {
            int s = w * 2 + lane;
            int idx = u0 + s;
            int tg  = dir ? (SRC - 1 - t) : t;
            const float* gi = gi_base + (size_t)tg * G3;
            float ghr = res[lane][0] + bsm[s * 3 + 0];
            float ghz = res[lane][1] + bsm[s * 3 + 1];
            float ghn = res[lane][2] + bsm[s * 3 + 2];
            float r = sigmoidf_(gi[idx] + ghr);
            float z = sigmoidf_(gi[H + idx] + ghz);
            float n = tanhf(gi[2 * H + idx] + r * ghn);
            float hp = g_henc[dir][p][idx];
            float h2 = (1.0f - z) * n + z * hp;
            outs[(size_t)tg * H + idx] = h2;
            g_henc[dir][p ^ 1][idx] = h2;
        }
        grid_barrier(&g_bar_e, (unsigned)(t + 1) * 128u);
    }
}

// ---------------- persistent decoder scan ----------------
// 128 blocks x 256 threads; each block owns 8 units (96KB smem), 1 unit/warp.
__global__ void __launch_bounds__(256, 1) dec_scan(const float* __restrict__ whh,
                                                   const float* __restrict__ bhh) {
    extern __shared__ float smem[];
    const int b = blockIdx.x;
    const int u0 = b * 8;
    float* wsm = smem;
    float* bsm = smem + 8 * 3 * 1024;

    for (int i = threadIdx.x; i < 8 * 3 * 1024; i += 256) {
        int s = i / G3, rem = i % G3, g = rem >> 10, c = rem & (H - 1);
        wsm[i] = whh[((size_t)(g * H + u0 + s)) * H + c];
    }
    if (threadIdx.x < 24) {
        int s = threadIdx.x / 3, g = threadIdx.x % 3;
        bsm[s * 3 + g] = bhh[g * H + u0 + s];
    }
    __syncthreads();

    const int lane = threadIdx.x & 31, w = threadIdx.x >> 5;

    for (int t = 0; t < TGT; t++) {
        const int p = t & 1;
        const float4* hc = (const float4*)g_hdec[p];
        float4 hv[8];
#pragma unroll
        for (int j = 0; j < 8; j++) hv[j] = hc[lane + j * 32];

        const float4* wr = (const float4*)(wsm + w * G3);
        const float4* wz = wr + 256;
        const float4* wn = wz + 256;
        float ar = 0.f, az = 0.f, an = 0.f;
#pragma unroll
        for (int j = 0; j < 8; j++) {
            float4 h4 = hv[j];
            float4 r4 = wr[lane + j * 32];
            ar += h4.x * r4.x + h4.y * r4.y + h4.z * r4.z + h4.w * r4.w;
            float4 z4 = wz[lane + j * 32];
            az += h4.x * z4.x + h4.y * z4.y + h4.z * z4.z + h4.w * z4.w;
            float4 n4 = wn[lane + j * 32];
            an += h4.x * n4.x + h4.y * n4.y + h4.z * n4.z + h4.w * n4.w;
        }
#pragma unroll
        for (int o = 16; o > 0; o >>= 1) {
            ar += __shfl_xor_sync(0xffffffffu, ar, o);
            az += __shfl_xor_sync(0xffffffffu, az, o);
            an += __shfl_xor_sync(0xffffffffu, an, o);
        }
        if (lane == 0) {
            int idx = u0 + w;
            const float* gi = g_GId + (size_t)t * G3;
            float ghr = ar + bsm[w * 3 + 0];
            float ghz = az + bsm[w * 3 + 1];
            float ghn = an + bsm[w * 3 + 2];
            float r = sigmoidf_(gi[idx] + ghr);
            float z = sigmoidf_(gi[H + idx] + ghz);
            float n = tanhf(gi[2 * H + idx] + r * ghn);
            float hp = g_hdec[p][idx];
            float h2 = (1.0f - z) * n + z * hp;
            g_H2[(size_t)t * H + idx] = h2;
            g_hdec[p ^ 1][idx] = h2;
        }
        grid_barrier(&g_bar_d, (unsigned)(t + 1) * 128u);
    }
}

// ---------------- log-softmax (in place, one block per row) ----------------
__global__ void __launch_bounds__(256) log_softmax_rows(float* __restrict__ x) {
    __shared__ float red[256];
    float* row = x + (size_t)blockIdx.x * VOUT;
    int tid = threadIdx.x;

    float m = -1e30f;
    for (int i = tid; i < VOUT; i += 256) m = fmaxf(m, row[i]);
    red[tid] = m; __syncthreads();
    for (int o = 128; o > 0; o >>= 1) {
        if (tid < o) red[tid] = fmaxf(red[tid], red[tid + o]);
        __syncthreads();
    }
    float M = red[0]; __syncthreads();

    float s = 0.0f;
    for (int i = tid; i < VOUT; i += 256) s += expf(row[i] - M);
    red[tid] = s; __syncthreads();
    for (int o = 128; o > 0; o >>= 1) {
        if (tid < o) red[tid] += red[tid + o];
        __syncthreads();
    }
    float lse = M + logf(red[0]); __syncthreads();

    for (int i = tid; i < VOUT; i += 256) row[i] -= lse;
}

// ---------------- launch ----------------
extern "C" void kernel_launch(void* const* d_in, const int* in_sizes, int n_in,
                              void* d_out, int out_size) {
    const int*   ctxi   = (const int*)d_in[0];
    const int*   wi     = (const int*)d_in[1];
    const int*   tgts   = (const int*)d_in[2];
    const float* rarnn  = (const float*)d_in[3];
    const float* encemb = (const float*)d_in[4];
    const float* wih_f  = (const float*)d_in[5];
    const float* whh_f  = (const float*)d_in[6];
    const float* bih_f  = (const float*)d_in[7];
    const float* bhh_f  = (const float*)d_in[8];
    const float* wih_b  = (const float*)d_in[9];
    const float* whh_b  = (const float*)d_in[10];
    const float* bih_b  = (const float*)d_in[11];
    const float* bhh_b  = (const float*)d_in[12];
    const float* decemb = (const float*)d_in[13];
    const float* dwih   = (const float*)d_in[14];
    const float* dwhh   = (const float*)d_in[15];
    const float* dbih   = (const float*)d_in[16];
    const float* dbhh   = (const float*)d_in[17];
    const float* outw   = (const float*)d_in[18];
    const float* outb   = (const float*)d_in[19];
    float* out = (float*)d_out;

    const int ENC_SMEM = (16 * 3 * 1024 + 64) * 4;
    const int DEC_SMEM = (8 * 3 * 1024 + 32) * 4;
    cudaFuncSetAttribute(enc_scan, cudaFuncAttributeMaxDynamicSharedMemorySize, ENC_SMEM);
    cudaFuncSetAttribute(dec_scan, cudaFuncAttributeMaxDynamicSharedMemorySize, DEC_SMEM);

    float *gX, *gGIf, *gGIb, *gXT, *gGId, *gH2, *gATT, *gCTX, *gCAT, *gEnc, *gEncT;
    cudaGetSymbolAddress((void**)&gX, g_X);
    cudaGetSymbolAddress((void**)&gGIf, g_GIf);
    cudaGetSymbolAddress((void**)&gGIb, g_GIb);
    cudaGetSymbolAddress((void**)&gXT, g_XT);
    cudaGetSymbolAddress((void**)&gGId, g_GId);
    cudaGetSymbolAddress((void**)&gH2, g_H2);
    cudaGetSymbolAddress((void**)&gATT, g_ATT);
    cudaGetSymbolAddress((void**)&gCTX, g_CTX);
    cudaGetSymbolAddress((void**)&gCAT, g_CAT);
    cudaGetSymbolAddress((void**)&gEnc, g_enc);
    cudaGetSymbolAddress((void**)&gEncT, g_encT);

    // init state + counters
    init_state<<<(4 * H + 255) / 256, 256>>>();

    // gathers
    gather_x<<<(SRC * H + 255) / 256, 256>>>(wi, encemb);
    build_xt<<<(TGT * 2 * H + 255) / 256, 256>>>(ctxi, tgts, rarnn, decemb);

    // precompute input gates (batch GEMMs)
    sgemm_nt<0><<<dim3(G3 / 128, SRC / 128), 256>>>(gX, wih_f, bih_f, gGIf, SRC, G3, H);
    sgemm_nt<0><<<dim3(G3 / 128, SRC / 128), 256>>>(gX, wih_b, bih_b, gGIb, SRC, G3, H);
    sgemm_nt<0><<<dim3(G3 / 128, TGT / 128), 256>>>(gXT, dwih, dbih, gGId, TGT, G3, 2 * H);

    // encoder recurrence (both directions), persistent
    enc_scan<<<128, 256, ENC_SMEM>>>(whh_f, whh_b, bhh_f, bhh_b);

    // enc_out, enc_out^T, dec_h0
    combine_enc<<<(SRC * H + 255) / 256, 256>>>();

    // decoder recurrence, persistent
    dec_scan<<<128, 256, DEC_SMEM>>>(dwhh, dbhh);

    // attention: A = sigmoid(H2 @ enc_out^T)  [128,512]
    sgemm_nt<1><<<dim3(SRC / 128, TGT / 128), 256>>>(gH2, gEnc, nullptr, gATT, TGT, SRC, H);
    // context = A @ enc_out  [128,1024]  (via enc_out^T as NT)
    sgemm_nt<0><<<dim3(H / 128, TGT / 128), 256>>>(gATT, gEncT, nullptr, gCTX, TGT, H, SRC);

    // logits = [H2|context] @ out_w^T + out_b -> directly into d_out
    build_cat<<<(TGT * 2 * H + 255) / 256, 256>>>();
    sgemm_nt<0><<<dim3(VOUT / 128, TGT / 128), 256>>>(gCAT, outw, outb, out, TGT, VOUT, 2 * H);

    // log_softmax in place
    log_softmax_rows<<<TGT, 256>>>(out);

    // attn outputs (first 127 rows)
    copy_attn<<<((TGT - 1) * SRC + 255) / 256, 256>>>(out);
}